// round 14
// baseline (speedup 1.0000x reference)
#include <cuda_runtime.h>
#include <cuda_fp16.h>
#include <cstdint>
#include <cstddef>

#define TLEN 4096
#define NB   32
#define HD   256
#define HS   264

// Scratch (device globals: allocation-free rule)
static __device__ __align__(256) float  g_Xp0[(size_t)TLEN * NB * HD];
static __device__ __align__(256) float  g_Xp1[(size_t)TLEN * NB * HD];
static __device__ __align__(256) __half g_H0h[(size_t)TLEN * NB * HD]; // [t][cid] 4KB k-major tiles
static __device__ int g_progA[8];    // [rank*4+cid] = t count published
static __device__ int g_progB[8];    // [par*4+cid]  = pairs of parity done
static __device__ int g_progG[16];   // [q*4+cid]    = tiles of stride-4 seq done

// ---------------------------------------------------------------------------
__device__ __forceinline__ float tanh_mufu(float x) {
    float y;
    asm("tanh.approx.f32 %0, %1;" : "=f"(y) : "f"(x));
    return y;
}
__device__ __forceinline__ uint32_t pack_h2(float lo, float hi) {
    __half2 h = __floats2half2_rn(lo, hi);
    return *reinterpret_cast<uint32_t*>(&h);
}
__device__ __forceinline__ uint32_t smem_u32(const void* p) {
    uint32_t a;
    asm("{ .reg .u64 t; cvta.to.shared.u64 t, %1; cvt.u32.u64 %0, t; }" : "=r"(a) : "l"(p));
    return a;
}
__device__ __forceinline__ uint32_t mapa_u32(uint32_t a, uint32_t r) {
    uint32_t d;
    asm("mapa.shared::cluster.u32 %0, %1, %2;" : "=r"(d) : "r"(a), "r"(r));
    return d;
}
__device__ __forceinline__ int ld_acq(const int* p) {
    int v;
    asm volatile("ld.acquire.gpu.global.s32 %0, [%1];" : "=r"(v) : "l"(p));
    return v;
}
__device__ __forceinline__ void st_rel(int* p, int v) {
    asm volatile("st.release.gpu.global.s32 [%0], %1;" :: "l"(p), "r"(v));
}
__device__ __forceinline__ int prewait(const int* p, int v) {
    int a;
    while ((a = ld_acq(p)) < v) { __nanosleep(200); }
    return a;
}
__device__ __forceinline__ void st_cluster32(uint32_t addr, uint32_t v) {
    asm volatile("st.shared::cluster.b32 [%0], %1;" :: "r"(addr), "r"(v) : "memory");
}
#define MB_INIT(a, c) asm volatile("mbarrier.init.shared.b64 [%0], %1;" :: "r"(a), "r"(c) : "memory")
__device__ __forceinline__ void arrive_local(uint32_t a) {
    asm volatile("mbarrier.arrive.shared.b64 _, [%0];" :: "r"(a) : "memory");
}
__device__ __forceinline__ void arrive_remote(uint32_t a) {
    asm volatile("mbarrier.arrive.release.cluster.shared::cluster.b64 _, [%0];"
                 :: "r"(a) : "memory");
}
__device__ __forceinline__ void mb_wait(uint32_t a, uint32_t parity) {
    asm volatile(
        "{\n\t.reg .pred P;\n\t"
        "W_%=:\n\t"
        "mbarrier.try_wait.parity.acquire.cluster.shared::cta.b64 P, [%0], %1, 0x989680;\n\t"
        "@P bra.uni D_%=;\n\t"
        "bra.uni W_%=;\n\t"
        "D_%=:\n\t}"
        :: "r"(a), "r"(parity) : "memory");
}
#define CLUSTER_SYNC() do {                                              \
    asm volatile("barrier.cluster.arrive.aligned;" ::: "memory");        \
    asm volatile("barrier.cluster.wait.aligned;" ::: "memory");          \
} while (0)
#define IOBAR() asm volatile("bar.sync 1, 256;" ::: "memory")

#define HMMA(acc, af, bf0, bf1)                                               \
    asm volatile(                                                             \
        "mma.sync.aligned.m16n8k16.row.col.f32.f16.f16.f32 "                  \
        "{%0,%1,%2,%3}, {%4,%5,%6,%7}, {%8,%9}, {%0,%1,%2,%3};"               \
        : "+f"((acc)[0]), "+f"((acc)[1]), "+f"((acc)[2]), "+f"((acc)[3])      \
        : "r"((af)[0]), "r"((af)[1]), "r"((af)[2]), "r"((af)[3]),             \
          "r"(bf0), "r"(bf1))
#define LDSM4(r0, r1, r2, r3, a)                                              \
    asm volatile("ldmatrix.sync.aligned.m8n8.x4.shared.b16 {%0,%1,%2,%3}, [%4];" \
        : "=r"(r0), "=r"(r1), "=r"(r2), "=r"(r3) : "r"(a))
#define LDSM4T(r0, r1, r2, r3, a)                                             \
    asm volatile("ldmatrix.sync.aligned.m8n8.x4.trans.shared.b16 {%0,%1,%2,%3}, [%4];" \
        : "=r"(r0), "=r"(r1), "=r"(r2), "=r"(r3) : "r"(a))

#define MMA_STEP16_2(c0, c1, afr, ab)                                         \
    do {                                                                      \
        _Pragma("unroll")                                                     \
        for (int kk = 0; kk < 8; ++kk) {                                      \
            uint32_t b0, b1, b2, b3;                                          \
            LDSM4(b0, b1, b2, b3, (ab) + kk * 64);                            \
            HMMA((c0), (afr)[2 * kk],     b0, b1);                            \
            HMMA((c1), (afr)[2 * kk + 1], b2, b3);                            \
        }                                                                     \
    } while (0)
#define MMA_STEP16T_2(c0, c1, afr, ab)                                        \
    do {                                                                      \
        _Pragma("unroll")                                                     \
        for (int kk = 0; kk < 8; ++kk) {                                      \
            uint32_t b0, b1, b2, b3;                                          \
            LDSM4T(b0, b1, b2, b3, (ab) + kk * 512);                          \
            HMMA((c0), (afr)[2 * kk],     b0, b1);                            \
            HMMA((c1), (afr)[2 * kk + 1], b2, b3);                            \
        }                                                                     \
    } while (0)

__device__ __forceinline__ void load_frags16(uint32_t afr[16][4],
                                             const float* __restrict__ W,
                                             int r0, int tid4) {
    #pragma unroll
    for (int kt = 0; kt < 16; ++kt) {
        const int k0 = kt * 16 + tid4 * 2;
        const float* p0 = W + (size_t)r0 * HD + k0;
        const float* p1 = W + (size_t)(r0 + 8) * HD + k0;
        afr[kt][0] = pack_h2(p0[0], p0[1]);
        afr[kt][1] = pack_h2(p1[0], p1[1]);
        afr[kt][2] = pack_h2(p0[8], p0[9]);
        afr[kt][3] = pack_h2(p1[8], p1[9]);
    }
}

// ---------------------------------------------------------------------------
__global__ void reset_flags_kernel() {
    const int t = threadIdx.x;
    if (t < 8)  { g_progA[t] = 0; g_progB[t] = 0; }
    if (t < 16) g_progG[t] = 0;
}

// ---------------------------------------------------------------------------
// grid = 40 CTAs x 512 thr, clusters of 2:
//  bx 0-7:  A (M-split pairs)  bx 8-15:  B (t-parity split)
//  bx 16-23:C (M-split pairs)  bx 24-39: G (t mod 4 split)
__global__ void __cluster_dims__(2, 1, 1) __launch_bounds__(512, 1)
rnn_fused_kernel(
    const float* __restrict__ xin,  const float* __restrict__ Wih0,
    const float* __restrict__ Whh0, const float* __restrict__ Whh1,
    const float* __restrict__ Wih1,
    const float* __restrict__ b_ih, const float* __restrict__ b_hh,
    const float* __restrict__ h0all, float* __restrict__ Out)
{
    __shared__ __align__(16) __half hsT[2][256][8];    // 8 KB
    __shared__ __align__(16) float  xbuf[3][1024];     // 12 KB (A/C xp ring)
    __shared__ __align__(16) float  obuf[2][8][132];   // 8.4 KB (C)
    __shared__ __align__(16) __half xs[2][8][HS];      // 8.4 KB (G)
    __shared__ __align__(8)  unsigned long long mbar[2];

    const int bx   = blockIdx.x;
    const int tid  = threadIdx.x;
    const int w    = tid >> 5;
    const int lane = tid & 31;
    const int grp  = lane >> 2;
    const int tid4 = lane & 3;
    const int n0   = tid4 * 2;

    const uint32_t hs_base = smem_u32(&hsT[0][0][0]);
    const uint32_t lsmT = hs_base + (uint32_t)lane * 16;

    // ======================= A / C: M-split recurrences =====================
    if (bx < 8 || (bx >= 16 && bx < 24)) {
        const bool isA = (bx < 8);
        const int cid  = (isA ? bx : bx - 16) >> 1;
        const int b0   = cid * 8;
        uint32_t crank;
        asm("mov.u32 %0, %%cluster_ctarank;" : "=r"(crank));
        const uint32_t mb_l = smem_u32(&mbar[0]);
        const uint32_t mb_r = mapa_u32(mb_l, crank ^ 1);
        const uint32_t hs_r = mapa_u32(hs_base, crank ^ 1);
        const float* Whh = isA ? Whh0 : Whh1;
        const float* Xp  = isA ? g_Xp0 : g_Xp1;
        const float* h0l = isA ? h0all : h0all + (size_t)NB * HD;

        if (tid == 0) { MB_INIT(mb_l, 768); MB_INIT(mb_l + 8, 768); }
        for (int idx = tid; idx < 2048; idx += 512) {
            const int k = idx >> 3, n = idx & 7;
            hsT[0][k][n] = __float2half_rn(h0l[(size_t)(b0 + n) * HD + k]);
        }
        if (tid >= 256) {   // I/O prologue: skid + stage xp(0), xp(1)
            if (tid == 256) {
                if (isA) {
                    for (int q = 0; q < 4; ++q) prewait(&g_progG[q * 4 + cid], 8);
                } else {
                    prewait(&g_progB[cid], 16);
                    prewait(&g_progB[4 + cid], 16);
                }
            }
            IOBAR();
            const int io = tid - 256;
            *(float4*)&xbuf[0][io * 4] =
                *(const float4*)(Xp + ((size_t)0 * 4 + cid) * 2048 + crank * 1024 + io * 4);
            *(float4*)&xbuf[1][io * 4] =
                *(const float4*)(Xp + ((size_t)1 * 4 + cid) * 2048 + crank * 1024 + io * 4);
        }
        __syncthreads();
        CLUSTER_SYNC();

        if (w < 8) {
            // ---------------- MMA warps ----------------
            const int m0g = (int)crank * 128 + w * 16 + grp;
            uint32_t afr[16][4];
            load_frags16(afr, Whh, m0g, tid4);
            int ph0 = 0, ph1 = 0, slot = 0;
            const int mloc = w * 16 + grp;

            for (int u = 0; u < TLEN; ++u) {
                const int rd = u & 1, wr2 = rd ^ 1;
                float4 xc = *(const float4*)&xbuf[slot][(w * 32 + lane) * 4];
                float c0[4], c1[4] = {};
                c0[0] = xc.x; c0[1] = xc.y; c0[2] = xc.z; c0[3] = xc.w;
                MMA_STEP16T_2(c0, c1, afr, lsmT + rd * 4096);

                float v0 = tanh_mufu(c0[0] + c1[0]);
                float v1 = tanh_mufu(c0[1] + c1[1]);
                float v2 = tanh_mufu(c0[2] + c1[2]);
                float v3 = tanh_mufu(c0[3] + c1[3]);
                uint32_t p01 = pack_h2(v0, v1), p23 = pack_h2(v2, v3);
                *(uint32_t*)&hsT[wr2][m0g][n0]     = p01;
                *(uint32_t*)&hsT[wr2][m0g + 8][n0] = p23;
                st_cluster32(hs_r + wr2 * 4096 + m0g * 16 + n0 * 2, p01);
                st_cluster32(hs_r + wr2 * 4096 + (m0g + 8) * 16 + n0 * 2, p23);
                if (!isA) {
                    obuf[wr2][n0][mloc]         = v0;
                    obuf[wr2][n0 + 1][mloc]     = v1;
                    obuf[wr2][n0][mloc + 8]     = v2;
                    obuf[wr2][n0 + 1][mloc + 8] = v3;
                }
                arrive_local(mb_l + wr2 * 8);
                arrive_remote(mb_r + wr2 * 8);
                mb_wait(mb_l + wr2 * 8, wr2 ? ph1 : ph0);
                if (wr2) ph1 ^= 1; else ph0 ^= 1;
                slot = (slot == 2) ? 0 : slot + 1;
            }
        } else {
            // ---------------- I/O warps ----------------
            const int io = tid - 256;
            int phio0 = 0, phio1 = 0;
            int av[4] = {8, 8, 8, 8};    // A: per-q G cache; C: [0..1] per-par B cache (=16)
            if (!isA) { av[0] = 16; av[1] = 16; }
            int ws = 2;                  // xbuf write slot = (u+2)%3

            for (int u = 0; u <= TLEN; ++u) {
                const int rd = u & 1, wr2 = rd ^ 1;
                if (u > 0) {
                    mb_wait(mb_l + rd * 8, rd ? phio1 : phio0);
                    if (rd) phio1 ^= 1; else phio0 ^= 1;
                    if (isA) {
                        uint2 v = *(const uint2*)((const char*)&hsT[0][0][0]
                                  + rd * 4096 + crank * 2048 + io * 8);
                        *(uint2*)((char*)g_H0h + (((size_t)(u - 1) * 4 + cid) * 4096)
                                  + crank * 2048 + io * 8) = v;
                    } else {
                        const int fn = io >> 5, fc = (io & 31) * 4;
                        float4 a = *(const float4*)&obuf[rd][fn][fc];
                        *(float4*)(Out + ((size_t)(u - 1) * NB + b0 + fn) * HD
                                   + crank * 128 + fc) = a;
                    }
                }
                if (u + 2 < TLEN) {
                    const int tn = u + 2;
                    if (isA) {
                        const int q = tn & 3, need = (tn >> 2) + 1;
                        if (av[q] < need)
                            while ((av[q] = ld_acq(&g_progG[q * 4 + cid])) < need) {}
                    } else {
                        const int p = tn >> 1, par = p & 1, need = (p >> 1) + 1;
                        if (av[par] < need)
                            while ((av[par] = ld_acq(&g_progB[par * 4 + cid])) < need) {}
                    }
                    *(float4*)&xbuf[ws][io * 4] =
                        *(const float4*)(Xp + ((size_t)tn * 4 + cid) * 2048
                                         + crank * 1024 + io * 4);
                }
                if (u < TLEN) arrive_local(mb_l + wr2 * 8);
                if (isA && u > 0) {
                    IOBAR();
                    if (io == 0 && ((u & 3) == 0 || u == TLEN))
                        st_rel(&g_progA[crank * 4 + cid], u);
                }
                ws = (ws == 2) ? 0 : ws + 1;
            }
        }
        CLUSTER_SYNC();
    }
    // ======================= B: xp1 projection (t-parity split) =============
    else if (bx < 16) {
        const int j = bx - 8, par = j >> 2, cid = j & 3;
        const int m0 = w * 16 + grp;
        uint32_t afr[16][4];
        load_frags16(afr, Wih1, m0, tid4);
        const float bias_lo = b_ih[HD + m0] + b_hh[HD + m0];
        const float bias_hi = b_ih[HD + m0 + 8] + b_hh[HD + m0 + 8];

        int av0 = 0, av1 = 0;
        if (tid == 0) {
            av0 = prewait(&g_progA[cid], 32);
            av1 = prewait(&g_progA[4 + cid], 32);
        }
        for (int pidx = 0; pidx < 1024; ++pidx) {
            const int tp = 4 * pidx + 2 * par;
            if (tid == 0) {
                if (av0 < tp + 2) while ((av0 = ld_acq(&g_progA[cid])) < tp + 2) {}
                if (av1 < tp + 2) while ((av1 = ld_acq(&g_progA[4 + cid])) < tp + 2) {}
            }
            __syncthreads();
            uint2 v0 = *(const uint2*)((const char*)g_H0h +
                        (((size_t)tp * 4 + cid) * 4096) + tid * 8);
            uint2 v1 = *(const uint2*)((const char*)g_H0h +
                        (((size_t)(tp + 1) * 4 + cid) * 4096) + tid * 8);
            *(uint2*)((char*)&hsT[0][0][0] + tid * 8) = v0;
            *(uint2*)((char*)&hsT[0][0][0] + 4096 + tid * 8) = v1;
            __syncthreads();
            #pragma unroll
            for (int s = 0; s < 2; ++s) {
                float c0[4], c1[4] = {};
                c0[0] = bias_lo; c0[1] = bias_lo; c0[2] = bias_hi; c0[3] = bias_hi;
                MMA_STEP16T_2(c0, c1, afr, lsmT + s * 4096);
                float4 o;
                o.x = c0[0] + c1[0];
                o.y = c0[1] + c1[1];
                o.z = c0[2] + c1[2];
                o.w = c0[3] + c1[3];
                *(float4*)(g_Xp1 +
                    (((size_t)(tp + s) * 4 + cid) * 16 + w) * 128 + lane * 4) = o;
            }
            __syncthreads();
            if (tid == 0 && (((pidx + 1) & 3) == 0 || pidx == 1023))
                st_rel(&g_progB[par * 4 + cid], pidx + 1);
        }
    }
    // ======================= G: xp0 input GEMM (t mod 4 split) ==============
    else {
        const int j = bx - 24, q = j >> 2, cid = j & 3;
        const int m0 = w * 16 + grp;
        uint32_t afr[16][4];
        load_frags16(afr, Wih0, m0, tid4);
        const float bias_lo = b_ih[m0] + b_hh[m0];
        const float bias_hi = b_ih[m0 + 8] + b_hh[m0 + 8];

        const uint32_t xs_base = smem_u32(&xs[0][0][0]);
        const uint32_t lsm = xs_base + (uint32_t)(lane & 7) * (HS * 2)
                                     + (uint32_t)(lane >> 3) * 16;
        const uint32_t XBUF = 8 * HS * 2;

        const int sn = tid >> 7, sk = (tid & 127) * 2;
        int tile = q * 4 + cid;          // flat tile of t=q

        {
            float2 a0 = *(const float2*)&xin[((size_t)tile * 8 + sn) * HD + sk];
            float2 a1 = *(const float2*)&xin[((size_t)tile * 8 + sn + 4) * HD + sk];
            *(uint32_t*)&xs[0][sn][sk]     = pack_h2(a0.x, a0.y);
            *(uint32_t*)&xs[0][sn + 4][sk] = pack_h2(a1.x, a1.y);
        }
        __syncthreads();

        for (int it = 0; it < 1024; ++it) {
            const int cur = it & 1, nxt = cur ^ 1;
            float2 a0, a1;
            if (it + 1 < 1024) {
                const size_t nb = ((size_t)(tile + 16) * 8 + sn) * HD + sk;
                a0 = *(const float2*)&xin[nb];
                a1 = *(const float2*)&xin[nb + 4 * HD];
            }
            float c0[4], c1[4] = {};
            c0[0] = bias_lo; c0[1] = bias_lo; c0[2] = bias_hi; c0[3] = bias_hi;
            MMA_STEP16_2(c0, c1, afr, lsm + cur * XBUF);
            if (it + 1 < 1024) {
                *(uint32_t*)&xs[nxt][sn][sk]     = pack_h2(a0.x, a0.y);
                *(uint32_t*)&xs[nxt][sn + 4][sk] = pack_h2(a1.x, a1.y);
            }
            float4 o;
            o.x = c0[0] + c1[0];
            o.y = c0[1] + c1[1];
            o.z = c0[2] + c1[2];
            o.w = c0[3] + c1[3];
            *(float4*)(g_Xp0 + ((size_t)tile * 16 + w) * 128 + lane * 4) = o;
            __syncthreads();
            if (tid == 0 && (((it + 1) & 3) == 0 || it + 1 == 1024))
                st_rel(&g_progG[q * 4 + cid], it + 1);
            tile += 16;
        }
    }
}

// -------------------------------- launcher ----------------------------------
extern "C" void kernel_launch(void* const* d_in, const int* in_sizes, int n_in,
                              void* d_out, int out_size) {
    const float* x    = (const float*)d_in[0];
    const float* W_ih = (const float*)d_in[1];
    const float* W_hh = (const float*)d_in[2];
    const float* b_ih = (const float*)d_in[3];
    const float* b_hh = (const float*)d_in[4];
    const float* h0   = (const float*)d_in[5];
    float* out = (float*)d_out;

    reset_flags_kernel<<<1, 32>>>();
    rnn_fused_kernel<<<40, 512>>>(x, W_ih,
                                  W_hh, W_hh + HD * HD, W_ih + HD * HD,
                                  b_ih, b_hh, h0, out);
}

// round 15
// speedup vs baseline: 1.1910x; 1.1910x over previous
#include <cuda_runtime.h>
#include <cuda_fp16.h>
#include <cstdint>
#include <cstddef>

#define TLEN 4096
#define NB   32
#define HD   256
#define HS   264   // G staging: halves per n-row (256 + 8 pad)

// Scratch (device globals: allocation-free rule)
static __device__ __align__(256) float  g_Xp0[(size_t)TLEN * NB * HD]; // frag-layout preacts L0
static __device__ __align__(256) float  g_Xp1[(size_t)TLEN * NB * HD]; // frag-layout preacts L1
static __device__ __align__(256) __half g_H0h[(size_t)TLEN * NB * HD]; // L0 hidden [t][cid][k][n]
static __device__ int g_progA[4];
static __device__ int g_progB[4];
static __device__ int g_progG[8];   // [par*4 + cid]

// ---------------------------------------------------------------------------
__device__ __forceinline__ float tanh_mufu(float x) {
    float y;
    asm("tanh.approx.f32 %0, %1;" : "=f"(y) : "f"(x));
    return y;
}
__device__ __forceinline__ uint32_t pack_h2(float lo, float hi) {
    __half2 h = __floats2half2_rn(lo, hi);
    return *reinterpret_cast<uint32_t*>(&h);
}
__device__ __forceinline__ uint32_t smem_u32(const void* p) {
    uint32_t a;
    asm("{ .reg .u64 t; cvta.to.shared.u64 t, %1; cvt.u32.u64 %0, t; }" : "=r"(a) : "l"(p));
    return a;
}
__device__ __forceinline__ int ld_acq(const int* p) {
    int v;
    asm volatile("ld.acquire.gpu.global.s32 %0, [%1];" : "=r"(v) : "l"(p));
    return v;
}
__device__ __forceinline__ void st_rel(int* p, int v) {
    asm volatile("st.release.gpu.global.s32 [%0], %1;" :: "l"(p), "r"(v));
}
__device__ __forceinline__ int prewait(const int* p, int v) {
    int a;
    while ((a = ld_acq(p)) < v) { __nanosleep(200); }
    return a;
}
#define HMMA(acc, af, bf0, bf1)                                               \
    asm volatile(                                                             \
        "mma.sync.aligned.m16n8k16.row.col.f32.f16.f16.f32 "                  \
        "{%0,%1,%2,%3}, {%4,%5,%6,%7}, {%8,%9}, {%0,%1,%2,%3};"               \
        : "+f"((acc)[0]), "+f"((acc)[1]), "+f"((acc)[2]), "+f"((acc)[3])      \
        : "r"((af)[0]), "r"((af)[1]), "r"((af)[2]), "r"((af)[3]),             \
          "r"(bf0), "r"(bf1))
#define LDSM4(r0, r1, r2, r3, a)                                              \
    asm volatile("ldmatrix.sync.aligned.m8n8.x4.shared.b16 {%0,%1,%2,%3}, [%4];" \
        : "=r"(r0), "=r"(r1), "=r"(r2), "=r"(r3) : "r"(a))
#define LDSM4T(r0, r1, r2, r3, a)                                             \
    asm volatile("ldmatrix.sync.aligned.m8n8.x4.trans.shared.b16 {%0,%1,%2,%3}, [%4];" \
        : "=r"(r0), "=r"(r1), "=r"(r2), "=r"(r3) : "r"(a))

// n-major (G): 8 LDSM4 + 16 HMMA, TWO depth-8 chains.
#define MMA_STEP16_2(c0, c1, afr, ab)                                         \
    do {                                                                      \
        _Pragma("unroll")                                                     \
        for (int kk = 0; kk < 8; ++kk) {                                      \
            uint32_t b0, b1, b2, b3;                                          \
            LDSM4(b0, b1, b2, b3, (ab) + kk * 64);                            \
            HMMA((c0), (afr)[2 * kk],     b0, b1);                            \
            HMMA((c1), (afr)[2 * kk + 1], b2, b3);                            \
        }                                                                     \
    } while (0)

// k-major (B): 8 LDSM4T + 16 HMMA, TWO depth-8 chains.
#define MMA_STEP16T_2(c0, c1, afr, ab)                                        \
    do {                                                                      \
        _Pragma("unroll")                                                     \
        for (int kk = 0; kk < 8; ++kk) {                                      \
            uint32_t b0, b1, b2, b3;                                          \
            LDSM4T(b0, b1, b2, b3, (ab) + kk * 512);                          \
            HMMA((c0), (afr)[2 * kk],     b0, b1);                            \
            HMMA((c1), (afr)[2 * kk + 1], b2, b3);                            \
        }                                                                     \
    } while (0)

// k-major (A/C recurrences): 8 LDSM4T + 16 HMMA, EIGHT depth-2 chains.
// kt -> chain kt & 7, so chain j accumulates kt = j and j + 8.
#define MMA_STEP16T_8(cc, afr, ab)                                            \
    do {                                                                      \
        _Pragma("unroll")                                                     \
        for (int kk = 0; kk < 8; ++kk) {                                      \
            uint32_t b0, b1, b2, b3;                                          \
            LDSM4T(b0, b1, b2, b3, (ab) + kk * 512);                          \
            HMMA((cc)[(2 * kk) & 7],     (afr)[2 * kk],     b0, b1);          \
            HMMA((cc)[(2 * kk + 1) & 7], (afr)[2 * kk + 1], b2, b3);          \
        }                                                                     \
    } while (0)

#define SUM8(cc, i) ((((cc)[0][i] + (cc)[1][i]) + ((cc)[2][i] + (cc)[3][i])) + \
                     (((cc)[4][i] + (cc)[5][i]) + ((cc)[6][i] + (cc)[7][i])))

// Register-resident A fragments for rows (r0, r0+8) of a 256x256 fp32 weight.
__device__ __forceinline__ void load_frags16(uint32_t afr[16][4],
                                             const float* __restrict__ W,
                                             int r0, int tid4) {
    #pragma unroll
    for (int kt = 0; kt < 16; ++kt) {
        const int k0 = kt * 16 + tid4 * 2;
        const float* p0 = W + (size_t)r0 * HD + k0;
        const float* p1 = W + (size_t)(r0 + 8) * HD + k0;
        afr[kt][0] = pack_h2(p0[0], p0[1]);
        afr[kt][1] = pack_h2(p1[0], p1[1]);
        afr[kt][2] = pack_h2(p0[8], p0[9]);
        afr[kt][3] = pack_h2(p1[8], p1[9]);
    }
}

// ---------------------------------------------------------------------------
// Flag reset (flags persist across graph replays; must run before fused kernel)
__global__ void reset_flags_kernel() {
    const int t = threadIdx.x;
    if (t < 4) { g_progA[t] = 0; g_progB[t] = 0; }
    if (t < 8) g_progG[t] = 0;
}

// ---------------------------------------------------------------------------
// Fused 4-stage pipelined kernel.  grid = 20 CTAs x 512 threads (16 warps):
//   CTA 0-3  (A): layer-0 recurrence     CTA 4-7  (B): xp1 projection
//   CTA 8-11 (C): layer-1 recurrence     CTA 12-19(G): xp0 input GEMM (t-ordered)
__global__ void __launch_bounds__(512, 1) rnn_fused_kernel(
    const float* __restrict__ xin,  const float* __restrict__ Wih0,
    const float* __restrict__ Whh0, const float* __restrict__ Whh1,
    const float* __restrict__ Wih1,
    const float* __restrict__ b_ih, const float* __restrict__ b_hh,
    const float* __restrict__ h0all, float* __restrict__ Out)
{
    __shared__ __align__(16) __half hsT[2][256][8];  // scan h state (k-major)
    __shared__ __align__(16) float  obuf[2][8][260]; // C: output staging
    __shared__ __align__(16) __half xs[2][8][HS];    // G: x staging

    const int bx   = blockIdx.x;
    const int tid  = threadIdx.x;
    const int w    = tid >> 5;
    const int lane = tid & 31;
    const int grp  = lane >> 2;
    const int tid4 = lane & 3;
    const int role = (bx < 12) ? (bx >> 2) : 3;   // 0=A,1=B,2=C,3=G
    const int cid  = bx & 3;
    const int b0   = cid * 8;
    const int m0   = w * 16 + grp;
    const int n0   = tid4 * 2;

    const uint32_t hs_base = smem_u32(&hsT[0][0][0]);
    const uint32_t lsmT = hs_base + (uint32_t)lane * 16;
    const uint32_t BUFB = 4096;

    // ======================= Stage A: layer-0 recurrence ====================
    if (role == 0) {
        uint32_t afr[16][4];
        load_frags16(afr, Whh0, m0, tid4);

        for (int idx = tid; idx < 2048; idx += 512) {
            const int k = idx >> 3, n = idx & 7;
            hsT[0][k][n] = __float2half_rn(h0all[(size_t)(b0 + n) * HD + k]);
        }
        __syncthreads();

        // skid: wait for G to produce 16 t's per parity (t < 32 available)
        int avG[2];
        avG[0] = prewait(&g_progG[cid], 16);
        avG[1] = prewait(&g_progG[4 + cid], 16);

        const size_t fb = ((size_t)cid * 16 + w) * 128 + lane * 4;
        float4 xa = *(const float4*)(g_Xp0 + fb);           // x(0)
        float4 xb = *(const float4*)(g_Xp0 + 8192 + fb);    // x(1)

        for (int u = 0; u <= TLEN; ++u) {
            const int rd = u & 1, wr = rd ^ 1;

            float cc[8][4];
            #pragma unroll
            for (int j = 1; j < 8; ++j)
                #pragma unroll
                for (int i = 0; i < 4; ++i) cc[j][i] = 0.0f;
            const float* x = (const float*)&xa;
            cc[0][0] = x[0]; cc[0][1] = x[1]; cc[0][2] = x[2]; cc[0][3] = x[3];
            if (u < TLEN) MMA_STEP16T_8(cc, afr, lsmT + rd * BUFB);

            // publish h0(u-1) behind the MMA drain (flat 4KB copy)
            if (u > 0) {
                uint2 v = *(const uint2*)((const char*)&hsT[rd][0][0] + tid * 8);
                *(uint2*)((char*)g_H0h +
                          (((size_t)(u - 1) * 4 + cid) * 4096) + tid * 8) = v;
            }

            if (u < TLEN) {
                const int tn = (u + 2 < TLEN) ? u + 2 : TLEN - 1;
                const int par = tn & 1, ii = tn >> 1;
                if (avG[par] <= ii) {
                    while ((avG[par] = ld_acq(&g_progG[par * 4 + cid])) <= ii) {}
                }
                float4 xn = *(const float4*)(g_Xp0 + (size_t)tn * 8192 + fb);

                float v0 = tanh_mufu(SUM8(cc, 0));   // (m0,   n0)
                float v1 = tanh_mufu(SUM8(cc, 1));   // (m0,   n0+1)
                float v2 = tanh_mufu(SUM8(cc, 2));   // (m0+8, n0)
                float v3 = tanh_mufu(SUM8(cc, 3));   // (m0+8, n0+1)
                *(uint32_t*)&hsT[wr][m0][n0]     = pack_h2(v0, v1);
                *(uint32_t*)&hsT[wr][m0 + 8][n0] = pack_h2(v2, v3);
                xa = xb; xb = xn;
            }
            __syncthreads();
            if (tid == 0 && u > 0 && ((u & 3) == 0 || u == TLEN))
                st_rel(&g_progA[cid], u);
        }
    }
    // ======================= Stage B: xp1 projection ========================
    else if (role == 1) {
        uint32_t afr[16][4];
        load_frags16(afr, Wih1, m0, tid4);
        const float bias_lo = b_ih[HD + m0] + b_hh[HD + m0];
        const float bias_hi = b_ih[HD + m0 + 8] + b_hh[HD + m0 + 8];

        int avA = 0;
        if (tid == 0) avA = prewait(&g_progA[cid], 32);

        for (int tp = 0; tp < TLEN; tp += 2) {
            if (tid == 0 && avA < tp + 2) {
                while ((avA = ld_acq(&g_progA[cid])) < tp + 2) {}
            }
            __syncthreads();

            // stage two h0 tiles (flat 4KB copies)
            uint2 v0 = *(const uint2*)((const char*)g_H0h +
                        (((size_t)tp * 4 + cid) * 4096) + tid * 8);
            uint2 v1 = *(const uint2*)((const char*)g_H0h +
                        (((size_t)(tp + 1) * 4 + cid) * 4096) + tid * 8);
            *(uint2*)((char*)&hsT[0][0][0] + tid * 8) = v0;
            *(uint2*)((char*)&hsT[0][0][0] + 4096 + tid * 8) = v1;
            __syncthreads();

            #pragma unroll
            for (int s = 0; s < 2; ++s) {
                float c0[4], c1[4] = {};
                c0[0] = bias_lo; c0[1] = bias_lo; c0[2] = bias_hi; c0[3] = bias_hi;
                MMA_STEP16T_2(c0, c1, afr, lsmT + s * BUFB);
                float4 o;
                o.x = c0[0] + c1[0];
                o.y = c0[1] + c1[1];
                o.z = c0[2] + c1[2];
                o.w = c0[3] + c1[3];
                *(float4*)(g_Xp1 +
                    (((size_t)(tp + s) * 4 + cid) * 16 + w) * 128 + lane * 4) = o;
            }
            __syncthreads();
            if (tid == 0 && (((tp + 2) & 7) == 0 || tp + 2 == TLEN))
                st_rel(&g_progB[cid], tp + 2);
        }
    }
    // ======================= Stage C: layer-1 recurrence ====================
    else if (role == 2) {
        uint32_t afr[16][4];
        load_frags16(afr, Whh1, m0, tid4);

        const float* h0l1 = h0all + (size_t)NB * HD;
        for (int idx = tid; idx < 2048; idx += 512) {
            const int k = idx >> 3, n = idx & 7;
            hsT[0][k][n] = __float2half_rn(h0l1[(size_t)(b0 + n) * HD + k]);
        }
        __syncthreads();

        int avB = prewait(&g_progB[cid], 64);
        const size_t fb = ((size_t)cid * 16 + w) * 128 + lane * 4;
        float4 xa = *(const float4*)(g_Xp1 + fb);
        float4 xb = *(const float4*)(g_Xp1 + 8192 + fb);

        for (int u = 0; u <= TLEN; ++u) {
            const int rd = u & 1, wr = rd ^ 1;

            float cc[8][4];
            #pragma unroll
            for (int j = 1; j < 8; ++j)
                #pragma unroll
                for (int i = 0; i < 4; ++i) cc[j][i] = 0.0f;
            const float* x = (const float*)&xa;
            cc[0][0] = x[0]; cc[0][1] = x[1]; cc[0][2] = x[2]; cc[0][3] = x[3];
            if (u < TLEN) MMA_STEP16T_8(cc, afr, lsmT + rd * BUFB);

            // flush Out(u-1) behind the MMA drain (float4 per thread)
            if (u > 0) {
                const int fn = tid >> 6, fc = (tid & 63) * 4;
                float4 a = *(const float4*)&obuf[rd][fn][fc];
                *(float4*)(Out + ((size_t)(u - 1) * NB + b0 + fn) * HD + fc) = a;
            }

            if (u < TLEN) {
                const int tn = (u + 2 < TLEN) ? u + 2 : TLEN - 1;
                if (avB < tn + 1) {
                    while ((avB = ld_acq(&g_progB[cid])) < tn + 1) {}
                }
                float4 xn = *(const float4*)(g_Xp1 + (size_t)tn * 8192 + fb);

                float v0 = tanh_mufu(SUM8(cc, 0));
                float v1 = tanh_mufu(SUM8(cc, 1));
                float v2 = tanh_mufu(SUM8(cc, 2));
                float v3 = tanh_mufu(SUM8(cc, 3));
                *(uint32_t*)&hsT[wr][m0][n0]     = pack_h2(v0, v1);
                *(uint32_t*)&hsT[wr][m0 + 8][n0] = pack_h2(v2, v3);
                obuf[wr][n0][m0]         = v0;
                obuf[wr][n0 + 1][m0]     = v1;
                obuf[wr][n0][m0 + 8]     = v2;
                obuf[wr][n0 + 1][m0 + 8] = v3;
                xa = xb; xb = xn;
            }
            __syncthreads();
        }
    }
    // ======================= Stage G: xp0 input GEMM ========================
    else {
        const int j    = bx - 12;      // 0..7
        const int gcid = j & 3;
        const int par  = j >> 2;       // t parity this CTA produces

        uint32_t afr[16][4];
        load_frags16(afr, Wih0, m0, tid4);
        const float bias_lo = b_ih[m0] + b_hh[m0];
        const float bias_hi = b_ih[m0 + 8] + b_hh[m0 + 8];

        const uint32_t xs_base = smem_u32(&xs[0][0][0]);
        const uint32_t lsm = xs_base + (uint32_t)(lane & 7) * (HS * 2)
                                     + (uint32_t)(lane >> 3) * 16;
        const uint32_t XBUF = 8 * HS * 2;

        const int sn = tid >> 7, sk = (tid & 127) * 2;   // rows {sn, sn+4}
        int tile = par * 4 + gcid;                       // t = par

        {
            float2 a0 = *(const float2*)&xin[((size_t)tile * 8 + sn) * HD + sk];
            float2 a1 = *(const float2*)&xin[((size_t)tile * 8 + sn + 4) * HD + sk];
            *(uint32_t*)&xs[0][sn][sk]     = pack_h2(a0.x, a0.y);
            *(uint32_t*)&xs[0][sn + 4][sk] = pack_h2(a1.x, a1.y);
        }
        __syncthreads();

        for (int it = 0; it < 2048; ++it) {
            const int cur = it & 1, nxt = cur ^ 1;

            float2 a0, a1;
            if (it + 1 < 2048) {
                const size_t nb = ((size_t)(tile + 8) * 8 + sn) * HD + sk;
                a0 = *(const float2*)&xin[nb];
                a1 = *(const float2*)&xin[nb + 4 * HD];
            }

            float c0[4], c1[4] = {};
            c0[0] = bias_lo; c0[1] = bias_lo; c0[2] = bias_hi; c0[3] = bias_hi;
            MMA_STEP16_2(c0, c1, afr, lsm + cur * XBUF);

            if (it + 1 < 2048) {
                *(uint32_t*)&xs[nxt][sn][sk]     = pack_h2(a0.x, a0.y);
                *(uint32_t*)&xs[nxt][sn + 4][sk] = pack_h2(a1.x, a1.y);
            }

            float4 o;
            o.x = c0[0] + c1[0];
            o.y = c0[1] + c1[1];
            o.z = c0[2] + c1[2];
            o.w = c0[3] + c1[3];
            *(float4*)(g_Xp0 + ((size_t)tile * 16 + w) * 128 + lane * 4) = o;
            __syncthreads();
            if (tid == 0 && (((it + 1) & 3) == 0 || it + 1 == 2048))
                st_rel(&g_progG[j], it + 1);
            tile += 8;   // next t of this parity
        }
    }
}

// -------------------------------- launcher ----------------------------------
extern "C" void kernel_launch(void* const* d_in, const int* in_sizes, int n_in,
                              void* d_out, int out_size) {
    const float* x    = (const float*)d_in[0];  // [T,B,D]
    const float* W_ih = (const float*)d_in[1];  // [L,H,D]
    const float* W_hh = (const float*)d_in[2];  // [L,H,H]
    const float* b_ih = (const float*)d_in[3];  // [L,H]
    const float* b_hh = (const float*)d_in[4];  // [L,H]
    const float* h0   = (const float*)d_in[5];  // [L,B,H]
    float* out = (float*)d_out;                 // [T,B,H]

    reset_flags_kernel<<<1, 32>>>();
    rnn_fused_kernel<<<20, 512>>>(x, W_ih,
                                  W_hh, W_hh + HD * HD, W_ih + HD * HD,
                                  b_ih, b_hh, h0, out);
}